// round 14
// baseline (speedup 1.0000x reference)
#include <cuda_runtime.h>
#include <cuda_bf16.h>

// BilateralGridCP4D fused eval.
// Round-14: group-of-2 points per pipeline stage with float2 input loads.
// Scalar 12B-stride loads cost 3 wavefronts each (span 3 lines); float2 pair
// loads cut input wavefronts 18 -> 6 per point. Keeps R10's proven guarded
// depth-1 prefetch rotation (guards = code-motion barriers containing regs).
// No cache hints (R13: +8 regs, zero perf).

#define RANK 5
#define THREADS 256
#define GITER 4   // groups of 2 points per thread -> 8 points/thread

// layout: [0..59] fac0 native (12,5) row-major, [60..83] w1 (8,3),
//         [84..91] b1, [92..99] w2, [100] b2
__constant__ float c_params[104];
__device__   float g_staging[104];

__global__ void setup_kernel(const float* __restrict__ fac0,
                             const float* __restrict__ w1,
                             const float* __restrict__ b1,
                             const float* __restrict__ w2,
                             const float* __restrict__ b2)
{
    int t = threadIdx.x;
    if (t < 60)        g_staging[t] = fac0[t];
    else if (t < 84)   g_staging[t] = w1[t - 60];
    else if (t < 92)   g_staging[t] = b1[t - 84];
    else if (t < 100)  g_staging[t] = w2[t - 92];
    else if (t == 100) g_staging[100] = b2[0];
}

// pt[i*RANK + r] = (f0, f1-f0); val = f0 + w*delta. pos pre-clamped.
__device__ __forceinline__ void interp_mul_pt(const float2* __restrict__ pt,
                                              float pos, float coef[RANK], bool first)
{
    int i0 = (int)pos;
    float w = pos - (float)i0;
    const float2* p = pt + i0 * RANK;
#pragma unroll
    for (int r = 0; r < RANK; r++) {
        float2 f = p[r];
        float val = fmaf(w, f.y, f.x);
        if (first) coef[r] = val;
        else       coef[r] *= val;
    }
}

// Full single-point evaluation -> 3 float4 stores at point index i.
__device__ __forceinline__ void eval_point(float x, float y, float z,
                                           float r0, float g0, float b0,
                                           const float2* s_t1, const float2* s_t2,
                                           const float2* s_t3, const float2* s_t4,
                                           float4* __restrict__ out4, int i)
{
    // ---- rgb -> gray MLP (scalar constant reads -> LDCU uniform path) ----
    float acc = c_params[100];
#pragma unroll
    for (int h = 0; h < 8; h++) {
        float hv = fmaf(c_params[60 + h * 3 + 0], r0,
                   fmaf(c_params[60 + h * 3 + 1], g0,
                   fmaf(c_params[60 + h * 3 + 2], b0, c_params[84 + h])));
        hv = fmaxf(hv, 0.0f);
        acc = fmaf(c_params[92 + h], hv, acc);
    }
    // gray = tanh(2*acc) = 1 - t, t = 2/(exp(4*acc)+1)
    float e = __expf(4.0f * acc);
    float t = __fdividef(2.0f, e + 1.0f);

    // ---- positions (pos = v*0.25*(D-1) + 0.5*(D-1), BOUND=2) ----
    const float HI8  = 6.9999995f;
    const float HI16 = 14.999999f;
    float p1 = fminf(fmaxf(fmaf(x, 1.75f, 3.5f), 0.0f), HI8);
    float p2 = fminf(fmaxf(fmaf(y, 3.75f, 7.5f), 0.0f), HI16);
    float p3 = fminf(fmaxf(fmaf(z, 3.75f, 7.5f), 0.0f), HI16);
    float p4 = fminf(fmaf(-7.5f, t, 15.0f), HI16);   // gray axis, pos >= 0

    float coef[RANK];
    interp_mul_pt(s_t1, p1, coef, true);
    interp_mul_pt(s_t2, p2, coef, false);
    interp_mul_pt(s_t3, p3, coef, false);
    interp_mul_pt(s_t4, p4, coef, false);

    // ---- 5 -> 12 linear, fac0 native (12,5), scalar LDCU reads ----
    float4 o[3];
#pragma unroll
    for (int q = 0; q < 3; q++) {
        o[q].x = coef[0] * c_params[(4 * q + 0) * RANK];
        o[q].y = coef[0] * c_params[(4 * q + 1) * RANK];
        o[q].z = coef[0] * c_params[(4 * q + 2) * RANK];
        o[q].w = coef[0] * c_params[(4 * q + 3) * RANK];
    }
#pragma unroll
    for (int r = 1; r < RANK; r++) {
#pragma unroll
        for (int q = 0; q < 3; q++) {
            o[q].x = fmaf(coef[r], c_params[(4 * q + 0) * RANK + r], o[q].x);
            o[q].y = fmaf(coef[r], c_params[(4 * q + 1) * RANK + r], o[q].y);
            o[q].z = fmaf(coef[r], c_params[(4 * q + 2) * RANK + r], o[q].z);
            o[q].w = fmaf(coef[r], c_params[(4 * q + 3) * RANK + r], o[q].w);
        }
    }

    int base = 3 * i;
    out4[base + 0] = o[0];
    out4[base + 1] = o[1];
    out4[base + 2] = o[2];
}

__global__ __launch_bounds__(THREADS)
void bgrid_cp4d_kernel(const float2* __restrict__ xyz2,
                       const float2* __restrict__ rgb2,
                       const float* __restrict__ fac1,  // (5,8)
                       const float* __restrict__ fac2,  // (5,16)
                       const float* __restrict__ fac3,  // (5,16)
                       const float* __restrict__ fac4,  // (5,16)
                       float4* __restrict__ out4,       // N*3 float4
                       int ngrp)                         // N/2 point-pairs
{
    __shared__ float2 s_t1[7 * RANK];    // D=8
    __shared__ float2 s_t2[15 * RANK];   // D=16
    __shared__ float2 s_t3[15 * RANK];
    __shared__ float2 s_t4[15 * RANK];

    int tid = threadIdx.x;
    if (tid < 35) {
        int i = tid / RANK, r = tid % RANK;
        float a = fac1[r * 8 + i], b = fac1[r * 8 + i + 1];
        s_t1[tid] = make_float2(a, b - a);
    }
    if (tid < 75) {
        int i = tid / RANK, r = tid % RANK;
        float a = fac2[r * 16 + i], b = fac2[r * 16 + i + 1];
        s_t2[tid] = make_float2(a, b - a);
    } else if (tid < 150) {
        int k = tid - 75, i = k / RANK, r = k % RANK;
        float a = fac3[r * 16 + i], b = fac3[r * 16 + i + 1];
        s_t3[k] = make_float2(a, b - a);
    } else if (tid < 225) {
        int k = tid - 150, i = k / RANK, r = k % RANK;
        float a = fac4[r * 16 + i], b = fac4[r * 16 + i + 1];
        s_t4[k] = make_float2(a, b - a);
    }
    __syncthreads();

    const int gstride = gridDim.x * THREADS;
    int g = blockIdx.x * THREADS + tid;
    if (g >= ngrp) return;

    // prologue: 6 float2 loads cover 2 points' xyz+rgb (48 B, 2-line spans)
    float2 a0 = xyz2[3 * g + 0];   // x0 y0
    float2 a1 = xyz2[3 * g + 1];   // z0 x1
    float2 a2 = xyz2[3 * g + 2];   // y1 z1
    float2 c0 = rgb2[3 * g + 0];
    float2 c1 = rgb2[3 * g + 1];
    float2 c2 = rgb2[3 * g + 2];

#pragma unroll
    for (int k = 0; k < GITER; k++) {
        // ---- prefetch next group's inputs ----
        float2 na0, na1, na2, nc0, nc1, nc2;
        int gn = g + gstride;
        if (k + 1 < GITER) {
            int gp = (gn < ngrp) ? gn : g;   // safe addr, discarded if OOB
            na0 = xyz2[3 * gp + 0];
            na1 = xyz2[3 * gp + 1];
            na2 = xyz2[3 * gp + 2];
            nc0 = rgb2[3 * gp + 0];
            nc1 = rgb2[3 * gp + 1];
            nc2 = rgb2[3 * gp + 2];
        }

        // ---- evaluate the 2 points of this group ----
        eval_point(a0.x, a0.y, a1.x, c0.x, c0.y, c1.x,
                   s_t1, s_t2, s_t3, s_t4, out4, 2 * g + 0);
        eval_point(a1.y, a2.x, a2.y, c1.y, c2.x, c2.y,
                   s_t1, s_t2, s_t3, s_t4, out4, 2 * g + 1);

        // ---- rotate pipeline (guards double as code-motion barriers) ----
        if (k + 1 < GITER) {
            if (gn >= ngrp) return;
            g = gn;
            a0 = na0; a1 = na1; a2 = na2;
            c0 = nc0; c1 = nc1; c2 = nc2;
        }
    }
}

extern "C" void kernel_launch(void* const* d_in, const int* in_sizes, int n_in,
                              void* d_out, int out_size)
{
    const float2* xyz2 = (const float2*)d_in[0];
    const float2* rgb2 = (const float2*)d_in[1];
    const float*  fac1 = (const float*)d_in[3];
    const float*  fac2 = (const float*)d_in[4];
    const float*  fac3 = (const float*)d_in[5];
    const float*  fac4 = (const float*)d_in[6];
    float4* out4 = (float4*)d_out;

    // Gather uniform params (one kernel node) then one memcpy into constant.
    setup_kernel<<<1, 128>>>((const float*)d_in[2], (const float*)d_in[7],
                             (const float*)d_in[8], (const float*)d_in[9],
                             (const float*)d_in[10]);
    void* staging_ptr = nullptr;
    cudaGetSymbolAddress(&staging_ptr, g_staging);
    cudaMemcpyToSymbolAsync(c_params, staging_ptr, 101 * sizeof(float), 0,
                            cudaMemcpyDeviceToDevice, 0);

    int npts = in_sizes[0] / 3;    // N = 2^22 (even)
    int ngrp = npts / 2;           // point-pairs
    int per_block = THREADS * GITER;
    int blocks = (ngrp + per_block - 1) / per_block;
    bgrid_cp4d_kernel<<<blocks, THREADS>>>(xyz2, rgb2, fac1, fac2, fac3, fac4,
                                           out4, ngrp);
}

// round 15
// speedup vs baseline: 1.7540x; 1.7540x over previous
#include <cuda_runtime.h>
#include <cuda_fp16.h>
#include <cuda_bf16.h>

// BilateralGridCP4D fused eval.
// Round-15: champion R10 structure (1pt/stage, ITER=4 guarded pipeline,
// constant params via scalar LDCU) + fp16 gather tables: (f0, delta) stored
// as half2 -> 20 divergent LDS.32 instead of 20 LDS.64, halving the gather
// wavefronts (the dominant irreducible L1tex term, 40 of ~94 wf/pt).
// Inputs/outputs/weights/final math all stay fp32.

#define RANK 5
#define THREADS 256
#define ITER 4

// layout: [0..59] fac0 native (12,5) row-major, [60..83] w1 (8,3),
//         [84..91] b1, [92..99] w2, [100] b2
__constant__ float c_params[104];
__device__   float g_staging[104];

__global__ void setup_kernel(const float* __restrict__ fac0,
                             const float* __restrict__ w1,
                             const float* __restrict__ b1,
                             const float* __restrict__ w2,
                             const float* __restrict__ b2)
{
    int t = threadIdx.x;
    if (t < 60)        g_staging[t] = fac0[t];
    else if (t < 84)   g_staging[t] = w1[t - 60];
    else if (t < 92)   g_staging[t] = b1[t - 84];
    else if (t < 100)  g_staging[t] = w2[t - 92];
    else if (t == 100) g_staging[100] = b2[0];
}

// pt[i*RANK + r] = half2(f0, f1-f0); val = f0 + w*delta (fp32 math).
// pos pre-clamped so (int)pos <= D-2.
__device__ __forceinline__ void interp_mul_pt(const __half2* __restrict__ pt,
                                              float pos, float coef[RANK], bool first)
{
    int i0 = (int)pos;
    float w = pos - (float)i0;
    const __half2* p = pt + i0 * RANK;
#pragma unroll
    for (int r = 0; r < RANK; r++) {
        float2 f = __half22float2(p[r]);
        float val = fmaf(w, f.y, f.x);
        if (first) coef[r] = val;
        else       coef[r] *= val;
    }
}

__global__ __launch_bounds__(THREADS)
void bgrid_cp4d_kernel(const float* __restrict__ xyz,
                       const float* __restrict__ rgb,
                       const float* __restrict__ fac1,  // (5,8)
                       const float* __restrict__ fac2,  // (5,16)
                       const float* __restrict__ fac3,  // (5,16)
                       const float* __restrict__ fac4,  // (5,16)
                       float4* __restrict__ out4,       // N*3 float4
                       int npts)
{
    __shared__ __half2 s_t1[7 * RANK];    // D=8
    __shared__ __half2 s_t2[15 * RANK];   // D=16
    __shared__ __half2 s_t3[15 * RANK];
    __shared__ __half2 s_t4[15 * RANK];

    int tid = threadIdx.x;
    if (tid < 35) {
        int i = tid / RANK, r = tid % RANK;
        float a = fac1[r * 8 + i], b = fac1[r * 8 + i + 1];
        s_t1[tid] = __floats2half2_rn(a, b - a);
    }
    if (tid < 75) {
        int i = tid / RANK, r = tid % RANK;
        float a = fac2[r * 16 + i], b = fac2[r * 16 + i + 1];
        s_t2[tid] = __floats2half2_rn(a, b - a);
    } else if (tid < 150) {
        int k = tid - 75, i = k / RANK, r = k % RANK;
        float a = fac3[r * 16 + i], b = fac3[r * 16 + i + 1];
        s_t3[k] = __floats2half2_rn(a, b - a);
    } else if (tid < 225) {
        int k = tid - 150, i = k / RANK, r = k % RANK;
        float a = fac4[r * 16 + i], b = fac4[r * 16 + i + 1];
        s_t4[k] = __floats2half2_rn(a, b - a);
    }
    __syncthreads();

    const int stride = gridDim.x * THREADS;
    int i = blockIdx.x * THREADS + tid;
    if (i >= npts) return;

    // prologue: load inputs for first point
    float x  = xyz[3 * i + 0];
    float y  = xyz[3 * i + 1];
    float z  = xyz[3 * i + 2];
    float r0 = rgb[3 * i + 0];
    float g0 = rgb[3 * i + 1];
    float b0 = rgb[3 * i + 2];

#pragma unroll
    for (int k = 0; k < ITER; k++) {
        // ---- prefetch next iteration's inputs ----
        float xn, yn, zn, rn, gn, bn;
        int inext = i + stride;
        if (k + 1 < ITER) {
            int ip = (inext < npts) ? inext : i;   // safe addr, discarded if OOB
            xn = xyz[3 * ip + 0];
            yn = xyz[3 * ip + 1];
            zn = xyz[3 * ip + 2];
            rn = rgb[3 * ip + 0];
            gn = rgb[3 * ip + 1];
            bn = rgb[3 * ip + 2];
        }

        // ---- rgb -> gray MLP (scalar constant reads -> LDCU uniform path) ----
        float acc = c_params[100];
#pragma unroll
        for (int h = 0; h < 8; h++) {
            float hv = fmaf(c_params[60 + h * 3 + 0], r0,
                       fmaf(c_params[60 + h * 3 + 1], g0,
                       fmaf(c_params[60 + h * 3 + 2], b0, c_params[84 + h])));
            hv = fmaxf(hv, 0.0f);
            acc = fmaf(c_params[92 + h], hv, acc);
        }
        // gray = tanh(2*acc) = 1 - t, t = 2/(exp(4*acc)+1)
        float e = __expf(4.0f * acc);
        float t = __fdividef(2.0f, e + 1.0f);

        // ---- positions (pos = v*0.25*(D-1) + 0.5*(D-1), BOUND=2) ----
        const float HI8  = 6.9999995f;
        const float HI16 = 14.999999f;
        float p1 = fminf(fmaxf(fmaf(x, 1.75f, 3.5f), 0.0f), HI8);
        float p2 = fminf(fmaxf(fmaf(y, 3.75f, 7.5f), 0.0f), HI16);
        float p3 = fminf(fmaxf(fmaf(z, 3.75f, 7.5f), 0.0f), HI16);
        float p4 = fminf(fmaf(-7.5f, t, 15.0f), HI16);  // gray axis, pos >= 0

        float coef[RANK];
        interp_mul_pt(s_t1, p1, coef, true);
        interp_mul_pt(s_t2, p2, coef, false);
        interp_mul_pt(s_t3, p3, coef, false);
        interp_mul_pt(s_t4, p4, coef, false);

        // ---- 5 -> 12 linear, fac0 native (12,5), scalar LDCU reads ----
        float4 o[3];
#pragma unroll
        for (int q = 0; q < 3; q++) {
            o[q].x = coef[0] * c_params[(4 * q + 0) * RANK];
            o[q].y = coef[0] * c_params[(4 * q + 1) * RANK];
            o[q].z = coef[0] * c_params[(4 * q + 2) * RANK];
            o[q].w = coef[0] * c_params[(4 * q + 3) * RANK];
        }
#pragma unroll
        for (int r = 1; r < RANK; r++) {
#pragma unroll
            for (int q = 0; q < 3; q++) {
                o[q].x = fmaf(coef[r], c_params[(4 * q + 0) * RANK + r], o[q].x);
                o[q].y = fmaf(coef[r], c_params[(4 * q + 1) * RANK + r], o[q].y);
                o[q].z = fmaf(coef[r], c_params[(4 * q + 2) * RANK + r], o[q].z);
                o[q].w = fmaf(coef[r], c_params[(4 * q + 3) * RANK + r], o[q].w);
            }
        }

        int base = 3 * i;
        out4[base + 0] = o[0];
        out4[base + 1] = o[1];
        out4[base + 2] = o[2];

        // ---- rotate pipeline (guards double as code-motion barriers) ----
        if (k + 1 < ITER) {
            if (inext >= npts) return;
            i = inext;
            x = xn; y = yn; z = zn;
            r0 = rn; g0 = gn; b0 = bn;
        }
    }
}

extern "C" void kernel_launch(void* const* d_in, const int* in_sizes, int n_in,
                              void* d_out, int out_size)
{
    const float* xyz  = (const float*)d_in[0];
    const float* rgb  = (const float*)d_in[1];
    const float* fac1 = (const float*)d_in[3];
    const float* fac2 = (const float*)d_in[4];
    const float* fac3 = (const float*)d_in[5];
    const float* fac4 = (const float*)d_in[6];
    float4* out4 = (float4*)d_out;

    // Gather uniform params (one kernel node) then one memcpy into constant.
    setup_kernel<<<1, 128>>>((const float*)d_in[2], (const float*)d_in[7],
                             (const float*)d_in[8], (const float*)d_in[9],
                             (const float*)d_in[10]);
    void* staging_ptr = nullptr;
    cudaGetSymbolAddress(&staging_ptr, g_staging);
    cudaMemcpyToSymbolAsync(c_params, staging_ptr, 101 * sizeof(float), 0,
                            cudaMemcpyDeviceToDevice, 0);

    int npts = in_sizes[0] / 3;
    int per_block = THREADS * ITER;
    int blocks = (npts + per_block - 1) / per_block;
    bgrid_cp4d_kernel<<<blocks, THREADS>>>(xyz, rgb, fac1, fac2, fac3, fac4,
                                           out4, npts);
}

// round 16
// speedup vs baseline: 1.7560x; 1.0011x over previous
#include <cuda_runtime.h>
#include <cuda_fp16.h>
#include <cuda_bf16.h>

// BilateralGridCP4D fused eval.
// Round-16: R15 champion (ITER=4 guarded pipeline, fp16 (f0,delta) gather
// tables, constant params) + packed fma.rn.f32x2 for the 5->12 linear
// (60 FFMA -> 30 FFMA2; issue was 77% -- math slots now throttle the
// memory-request stream that sets the achieved DRAM rate).

#define RANK 5
#define THREADS 256
#define ITER 4

// layout: [0..59] fac0 TRANSPOSED r-major (idx = r*12 + j, pairs adjacent),
//         [60..83] w1 (8,3), [84..91] b1, [92..99] w2, [100] b2
__constant__ float c_params[104];
__device__   float g_staging[104];

using u64 = unsigned long long;

__device__ __forceinline__ u64 pack2(float a, float b) {
    u64 d; asm("mov.b64 %0,{%1,%2};" : "=l"(d) : "f"(a), "f"(b)); return d;
}
__device__ __forceinline__ u64 fma2(u64 a, u64 b, u64 c) {
    u64 d; asm("fma.rn.f32x2 %0,%1,%2,%3;" : "=l"(d) : "l"(a), "l"(b), "l"(c)); return d;
}
__device__ __forceinline__ u64 mul2(u64 a, u64 b) {
    u64 d; asm("mul.rn.f32x2 %0,%1,%2;" : "=l"(d) : "l"(a), "l"(b)); return d;
}

__global__ void setup_kernel(const float* __restrict__ fac0,
                             const float* __restrict__ w1,
                             const float* __restrict__ b1,
                             const float* __restrict__ w2,
                             const float* __restrict__ b2)
{
    int t = threadIdx.x;
    if (t < 60) {                        // fac0 transpose: [r][j] <- fac0[j][r]
        int r = t / 12, j = t % 12;
        g_staging[t] = fac0[j * RANK + r];
    }
    else if (t < 84)   g_staging[t] = w1[t - 60];
    else if (t < 92)   g_staging[t] = b1[t - 84];
    else if (t < 100)  g_staging[t] = w2[t - 92];
    else if (t == 100) g_staging[100] = b2[0];
}

// pt[i*RANK + r] = half2(f0, f1-f0); val = f0 + w*delta (fp32 math).
__device__ __forceinline__ void interp_mul_pt(const __half2* __restrict__ pt,
                                              float pos, float coef[RANK], bool first)
{
    int i0 = (int)pos;
    float w = pos - (float)i0;
    const __half2* p = pt + i0 * RANK;
#pragma unroll
    for (int r = 0; r < RANK; r++) {
        float2 f = __half22float2(p[r]);
        float val = fmaf(w, f.y, f.x);
        if (first) coef[r] = val;
        else       coef[r] *= val;
    }
}

__global__ __launch_bounds__(THREADS)
void bgrid_cp4d_kernel(const float* __restrict__ xyz,
                       const float* __restrict__ rgb,
                       const float* __restrict__ fac1,  // (5,8)
                       const float* __restrict__ fac2,  // (5,16)
                       const float* __restrict__ fac3,  // (5,16)
                       const float* __restrict__ fac4,  // (5,16)
                       float4* __restrict__ out4,       // N*3 float4
                       int npts)
{
    __shared__ __half2 s_t1[7 * RANK];    // D=8
    __shared__ __half2 s_t2[15 * RANK];   // D=16
    __shared__ __half2 s_t3[15 * RANK];
    __shared__ __half2 s_t4[15 * RANK];

    int tid = threadIdx.x;
    if (tid < 35) {
        int i = tid / RANK, r = tid % RANK;
        float a = fac1[r * 8 + i], b = fac1[r * 8 + i + 1];
        s_t1[tid] = __floats2half2_rn(a, b - a);
    }
    if (tid < 75) {
        int i = tid / RANK, r = tid % RANK;
        float a = fac2[r * 16 + i], b = fac2[r * 16 + i + 1];
        s_t2[tid] = __floats2half2_rn(a, b - a);
    } else if (tid < 150) {
        int k = tid - 75, i = k / RANK, r = k % RANK;
        float a = fac3[r * 16 + i], b = fac3[r * 16 + i + 1];
        s_t3[k] = __floats2half2_rn(a, b - a);
    } else if (tid < 225) {
        int k = tid - 150, i = k / RANK, r = k % RANK;
        float a = fac4[r * 16 + i], b = fac4[r * 16 + i + 1];
        s_t4[k] = __floats2half2_rn(a, b - a);
    }
    __syncthreads();

    const int stride = gridDim.x * THREADS;
    int i = blockIdx.x * THREADS + tid;
    if (i >= npts) return;

    // prologue: load inputs for first point
    float x  = xyz[3 * i + 0];
    float y  = xyz[3 * i + 1];
    float z  = xyz[3 * i + 2];
    float r0 = rgb[3 * i + 0];
    float g0 = rgb[3 * i + 1];
    float b0 = rgb[3 * i + 2];

#pragma unroll
    for (int k = 0; k < ITER; k++) {
        // ---- prefetch next iteration's inputs ----
        float xn, yn, zn, rn, gn, bn;
        int inext = i + stride;
        if (k + 1 < ITER) {
            int ip = (inext < npts) ? inext : i;   // safe addr, discarded if OOB
            xn = xyz[3 * ip + 0];
            yn = xyz[3 * ip + 1];
            zn = xyz[3 * ip + 2];
            rn = rgb[3 * ip + 0];
            gn = rgb[3 * ip + 1];
            bn = rgb[3 * ip + 2];
        }

        // ---- rgb -> gray MLP (scalar constant reads -> LDCU uniform path) ----
        float acc = c_params[100];
#pragma unroll
        for (int h = 0; h < 8; h++) {
            float hv = fmaf(c_params[60 + h * 3 + 0], r0,
                       fmaf(c_params[60 + h * 3 + 1], g0,
                       fmaf(c_params[60 + h * 3 + 2], b0, c_params[84 + h])));
            hv = fmaxf(hv, 0.0f);
            acc = fmaf(c_params[92 + h], hv, acc);
        }
        // gray = tanh(2*acc) = 1 - t, t = 2/(exp(4*acc)+1)
        float e = __expf(4.0f * acc);
        float t = __fdividef(2.0f, e + 1.0f);

        // ---- positions (pos = v*0.25*(D-1) + 0.5*(D-1), BOUND=2) ----
        const float HI8  = 6.9999995f;
        const float HI16 = 14.999999f;
        float p1 = fminf(fmaxf(fmaf(x, 1.75f, 3.5f), 0.0f), HI8);
        float p2 = fminf(fmaxf(fmaf(y, 3.75f, 7.5f), 0.0f), HI16);
        float p3 = fminf(fmaxf(fmaf(z, 3.75f, 7.5f), 0.0f), HI16);
        float p4 = fminf(fmaf(-7.5f, t, 15.0f), HI16);  // gray axis, pos >= 0

        float coef[RANK];
        interp_mul_pt(s_t1, p1, coef, true);
        interp_mul_pt(s_t2, p2, coef, false);
        interp_mul_pt(s_t3, p3, coef, false);
        interp_mul_pt(s_t4, p4, coef, false);

        // ---- 5 -> 12 linear, packed f32x2 (fac0^T pairs from constant) ----
        u64 op[6];
        {
            u64 cc = pack2(coef[0], coef[0]);
#pragma unroll
            for (int q = 0; q < 6; q++) {
                u64 f = *reinterpret_cast<const u64*>(&c_params[0 * 12 + 2 * q]);
                op[q] = mul2(cc, f);
            }
        }
#pragma unroll
        for (int r = 1; r < RANK; r++) {
            u64 cc = pack2(coef[r], coef[r]);
#pragma unroll
            for (int q = 0; q < 6; q++) {
                u64 f = *reinterpret_cast<const u64*>(&c_params[r * 12 + 2 * q]);
                op[q] = fma2(cc, f, op[q]);
            }
        }

        int base = 3 * i;
        // op[2q], op[2q+1] hold outputs (4q..4q+3); store as float4
        float2 lo, hi;
#pragma unroll
        for (int q = 0; q < 3; q++) {
            asm("mov.b64 {%0,%1},%2;" : "=f"(lo.x), "=f"(lo.y) : "l"(op[2 * q]));
            asm("mov.b64 {%0,%1},%2;" : "=f"(hi.x), "=f"(hi.y) : "l"(op[2 * q + 1]));
            out4[base + q] = make_float4(lo.x, lo.y, hi.x, hi.y);
        }

        // ---- rotate pipeline (guards double as code-motion barriers) ----
        if (k + 1 < ITER) {
            if (inext >= npts) return;
            i = inext;
            x = xn; y = yn; z = zn;
            r0 = rn; g0 = gn; b0 = bn;
        }
    }
}

extern "C" void kernel_launch(void* const* d_in, const int* in_sizes, int n_in,
                              void* d_out, int out_size)
{
    const float* xyz  = (const float*)d_in[0];
    const float* rgb  = (const float*)d_in[1];
    const float* fac1 = (const float*)d_in[3];
    const float* fac2 = (const float*)d_in[4];
    const float* fac3 = (const float*)d_in[5];
    const float* fac4 = (const float*)d_in[6];
    float4* out4 = (float4*)d_out;

    // Gather uniform params (one kernel node) then one memcpy into constant.
    setup_kernel<<<1, 128>>>((const float*)d_in[2], (const float*)d_in[7],
                             (const float*)d_in[8], (const float*)d_in[9],
                             (const float*)d_in[10]);
    void* staging_ptr = nullptr;
    cudaGetSymbolAddress(&staging_ptr, g_staging);
    cudaMemcpyToSymbolAsync(c_params, staging_ptr, 101 * sizeof(float), 0,
                            cudaMemcpyDeviceToDevice, 0);

    int npts = in_sizes[0] / 3;
    int per_block = THREADS * ITER;
    int blocks = (npts + per_block - 1) / per_block;
    bgrid_cp4d_kernel<<<blocks, THREADS>>>(xyz, rgb, fac1, fac2, fac3, fac4,
                                           out4, npts);
}

// round 17
// speedup vs baseline: 1.8011x; 1.0257x over previous
#include <cuda_runtime.h>
#include <cuda_fp16.h>
#include <cuda_bf16.h>

// BilateralGridCP4D fused eval.
// Round-17: R15 champion body (scalar math, fp16 (f0,delta) gather tables,
// constant params) with prefetch depth 2: while computing point k, the inputs
// of k+2 are in flight -> 12 outstanding LDGs/thread instead of 6. R13 proved
// the reg cost (~40) / occupancy cost (~65%) of this much state is rate-neutral,
// so the added memory-level parallelism is a pure upside bet on DRAM latency.

#define RANK 5
#define THREADS 256
#define ITER 4

// layout: [0..59] fac0 native (12,5) row-major, [60..83] w1 (8,3),
//         [84..91] b1, [92..99] w2, [100] b2
__constant__ float c_params[104];
__device__   float g_staging[104];

__global__ void setup_kernel(const float* __restrict__ fac0,
                             const float* __restrict__ w1,
                             const float* __restrict__ b1,
                             const float* __restrict__ w2,
                             const float* __restrict__ b2)
{
    int t = threadIdx.x;
    if (t < 60)        g_staging[t] = fac0[t];
    else if (t < 84)   g_staging[t] = w1[t - 60];
    else if (t < 92)   g_staging[t] = b1[t - 84];
    else if (t < 100)  g_staging[t] = w2[t - 92];
    else if (t == 100) g_staging[100] = b2[0];
}

// pt[i*RANK + r] = half2(f0, f1-f0); val = f0 + w*delta (fp32 math).
__device__ __forceinline__ void interp_mul_pt(const __half2* __restrict__ pt,
                                              float pos, float coef[RANK], bool first)
{
    int i0 = (int)pos;
    float w = pos - (float)i0;
    const __half2* p = pt + i0 * RANK;
#pragma unroll
    for (int r = 0; r < RANK; r++) {
        float2 f = __half22float2(p[r]);
        float val = fmaf(w, f.y, f.x);
        if (first) coef[r] = val;
        else       coef[r] *= val;
    }
}

// Full single-point evaluation -> 3 float4 stores at point index i.
__device__ __forceinline__ void eval_point(float x, float y, float z,
                                           float r0, float g0, float b0,
                                           const __half2* s_t1, const __half2* s_t2,
                                           const __half2* s_t3, const __half2* s_t4,
                                           float4* __restrict__ out4, int i)
{
    // ---- rgb -> gray MLP (scalar constant reads -> LDCU uniform path) ----
    float acc = c_params[100];
#pragma unroll
    for (int h = 0; h < 8; h++) {
        float hv = fmaf(c_params[60 + h * 3 + 0], r0,
                   fmaf(c_params[60 + h * 3 + 1], g0,
                   fmaf(c_params[60 + h * 3 + 2], b0, c_params[84 + h])));
        hv = fmaxf(hv, 0.0f);
        acc = fmaf(c_params[92 + h], hv, acc);
    }
    // gray = tanh(2*acc) = 1 - t, t = 2/(exp(4*acc)+1)
    float e = __expf(4.0f * acc);
    float t = __fdividef(2.0f, e + 1.0f);

    // ---- positions (pos = v*0.25*(D-1) + 0.5*(D-1), BOUND=2) ----
    const float HI8  = 6.9999995f;
    const float HI16 = 14.999999f;
    float p1 = fminf(fmaxf(fmaf(x, 1.75f, 3.5f), 0.0f), HI8);
    float p2 = fminf(fmaxf(fmaf(y, 3.75f, 7.5f), 0.0f), HI16);
    float p3 = fminf(fmaxf(fmaf(z, 3.75f, 7.5f), 0.0f), HI16);
    float p4 = fminf(fmaf(-7.5f, t, 15.0f), HI16);   // gray axis, pos >= 0

    float coef[RANK];
    interp_mul_pt(s_t1, p1, coef, true);
    interp_mul_pt(s_t2, p2, coef, false);
    interp_mul_pt(s_t3, p3, coef, false);
    interp_mul_pt(s_t4, p4, coef, false);

    // ---- 5 -> 12 linear, fac0 native (12,5), scalar LDCU reads ----
    float4 o[3];
#pragma unroll
    for (int q = 0; q < 3; q++) {
        o[q].x = coef[0] * c_params[(4 * q + 0) * RANK];
        o[q].y = coef[0] * c_params[(4 * q + 1) * RANK];
        o[q].z = coef[0] * c_params[(4 * q + 2) * RANK];
        o[q].w = coef[0] * c_params[(4 * q + 3) * RANK];
    }
#pragma unroll
    for (int r = 1; r < RANK; r++) {
#pragma unroll
        for (int q = 0; q < 3; q++) {
            o[q].x = fmaf(coef[r], c_params[(4 * q + 0) * RANK + r], o[q].x);
            o[q].y = fmaf(coef[r], c_params[(4 * q + 1) * RANK + r], o[q].y);
            o[q].z = fmaf(coef[r], c_params[(4 * q + 2) * RANK + r], o[q].z);
            o[q].w = fmaf(coef[r], c_params[(4 * q + 3) * RANK + r], o[q].w);
        }
    }

    int base = 3 * i;
    out4[base + 0] = o[0];
    out4[base + 1] = o[1];
    out4[base + 2] = o[2];
}

__global__ __launch_bounds__(THREADS)
void bgrid_cp4d_kernel(const float* __restrict__ xyz,
                       const float* __restrict__ rgb,
                       const float* __restrict__ fac1,  // (5,8)
                       const float* __restrict__ fac2,  // (5,16)
                       const float* __restrict__ fac3,  // (5,16)
                       const float* __restrict__ fac4,  // (5,16)
                       float4* __restrict__ out4,       // N*3 float4
                       int npts)
{
    __shared__ __half2 s_t1[7 * RANK];    // D=8
    __shared__ __half2 s_t2[15 * RANK];   // D=16
    __shared__ __half2 s_t3[15 * RANK];
    __shared__ __half2 s_t4[15 * RANK];

    int tid = threadIdx.x;
    if (tid < 35) {
        int i = tid / RANK, r = tid % RANK;
        float a = fac1[r * 8 + i], b = fac1[r * 8 + i + 1];
        s_t1[tid] = __floats2half2_rn(a, b - a);
    }
    if (tid < 75) {
        int i = tid / RANK, r = tid % RANK;
        float a = fac2[r * 16 + i], b = fac2[r * 16 + i + 1];
        s_t2[tid] = __floats2half2_rn(a, b - a);
    } else if (tid < 150) {
        int k = tid - 75, i = k / RANK, r = k % RANK;
        float a = fac3[r * 16 + i], b = fac3[r * 16 + i + 1];
        s_t3[k] = __floats2half2_rn(a, b - a);
    } else if (tid < 225) {
        int k = tid - 150, i = k / RANK, r = k % RANK;
        float a = fac4[r * 16 + i], b = fac4[r * 16 + i + 1];
        s_t4[k] = __floats2half2_rn(a, b - a);
    }
    __syncthreads();

    const int stride = gridDim.x * THREADS;
    int i = blockIdx.x * THREADS + tid;
    if (i >= npts) return;

    // prologue: depth-2 pipeline fill — load inputs for points 0 and 1
    float x0  = xyz[3 * i + 0];
    float y0  = xyz[3 * i + 1];
    float z0  = xyz[3 * i + 2];
    float r0  = rgb[3 * i + 0];
    float g0  = rgb[3 * i + 1];
    float b0  = rgb[3 * i + 2];

    int i1 = i + stride;
    int ip1 = (i1 < npts) ? i1 : i;
    float x1  = xyz[3 * ip1 + 0];
    float y1  = xyz[3 * ip1 + 1];
    float z1  = xyz[3 * ip1 + 2];
    float r1  = rgb[3 * ip1 + 0];
    float g1  = rgb[3 * ip1 + 1];
    float b1v = rgb[3 * ip1 + 2];

#pragma unroll
    for (int k = 0; k < ITER; k++) {
        // ---- prefetch inputs for point k+2 (12 LDGs now in flight) ----
        float x2, y2, z2, r2, g2, b2v;
        int i2 = i + 2 * stride;
        if (k + 2 < ITER) {
            int ip2 = (i2 < npts) ? i2 : i;   // safe addr, discarded if OOB
            x2  = xyz[3 * ip2 + 0];
            y2  = xyz[3 * ip2 + 1];
            z2  = xyz[3 * ip2 + 2];
            r2  = rgb[3 * ip2 + 0];
            g2  = rgb[3 * ip2 + 1];
            b2v = rgb[3 * ip2 + 2];
        }

        // ---- evaluate point k ----
        eval_point(x0, y0, z0, r0, g0, b0, s_t1, s_t2, s_t3, s_t4, out4, i);

        // ---- rotate pipeline (guards double as code-motion barriers) ----
        if (k + 1 < ITER) {
            int inext = i + stride;
            if (inext >= npts) return;
            i = inext;
            x0 = x1; y0 = y1; z0 = z1;
            r0 = r1; g0 = g1; b0 = b1v;
            if (k + 2 < ITER) {
                x1 = x2; y1 = y2; z1 = z2;
                r1 = r2; g1 = g2; b1v = b2v;
            }
        }
    }
}

extern "C" void kernel_launch(void* const* d_in, const int* in_sizes, int n_in,
                              void* d_out, int out_size)
{
    const float* xyz  = (const float*)d_in[0];
    const float* rgb  = (const float*)d_in[1];
    const float* fac1 = (const float*)d_in[3];
    const float* fac2 = (const float*)d_in[4];
    const float* fac3 = (const float*)d_in[5];
    const float* fac4 = (const float*)d_in[6];
    float4* out4 = (float4*)d_out;

    // Gather uniform params (one kernel node) then one memcpy into constant.
    setup_kernel<<<1, 128>>>((const float*)d_in[2], (const float*)d_in[7],
                             (const float*)d_in[8], (const float*)d_in[9],
                             (const float*)d_in[10]);
    void* staging_ptr = nullptr;
    cudaGetSymbolAddress(&staging_ptr, g_staging);
    cudaMemcpyToSymbolAsync(c_params, staging_ptr, 101 * sizeof(float), 0,
                            cudaMemcpyDeviceToDevice, 0);

    int npts = in_sizes[0] / 3;
    int per_block = THREADS * ITER;
    int blocks = (npts + per_block - 1) / per_block;
    bgrid_cp4d_kernel<<<blocks, THREADS>>>(xyz, rgb, fac1, fac2, fac3, fac4,
                                           out4, npts);
}